// round 5
// baseline (speedup 1.0000x reference)
#include <cuda_runtime.h>

#define TPB_M 256    // match kernel threads (one anchor each)
#define TPB_S 320    // sweep kernel threads (16 anchors x 20 float4)
#define NANN 32
#define NC 80
#define C4N 20       // float4 per anchor
#define MAXB 16
#define MAXK 131072

__device__ float g_acc[MAXB * 3];          // per image: cls_sum(+corr), reg_sum, num_pos
__device__ unsigned int g_count = 0;       // sweep-block completion counter (self-resetting)
__device__ float wbuf[MAXB * MAXK];        // per-anchor sweep weight (0 or COEF_NEG)

__device__ __forceinline__ float fsqrt_approx(float x) {
    float r; asm("sqrt.approx.f32 %0, %1;" : "=f"(r) : "f"(x)); return r;
}
__device__ __forceinline__ float flg2_approx(float x) {
    float r; asm("lg2.approx.f32 %0, %1;" : "=f"(r) : "f"(x)); return r;
}

#define LN2F 0.6931471805599453f
#define COEF_NEG (-0.75f * LN2F)    // term = COEF * sqrt(p) * lg2(1-p)
#define COEF_POS (-0.25f * LN2F)

// ---------------------------------------------------------------------------
// Kernel 1: IoU matching, weights, regression loss, positive-class correction
// ---------------------------------------------------------------------------
__global__ __launch_bounds__(TPB_M) void match_kernel(
    const float* __restrict__ cls,     // [B,K,C]
    const float* __restrict__ regs,    // [B,K,4]
    const float* __restrict__ anc,     // [1,K,4]
    const float* __restrict__ ann,     // [B,NANN,5]
    int K)
{
    const int b   = blockIdx.y;
    const int tid = threadIdx.x;
    const int k   = blockIdx.x * TPB_M + tid;

    __shared__ float4 s_box[NANN];
    __shared__ float  s_area[NANN];
    __shared__ float  s_lbl[NANN];
    __shared__ float  s_red[3][TPB_M / 32];

    if (tid < NANN) {
        const float* a = ann + (size_t)b * NANN * 5 + tid * 5;
        float x1 = a[0], y1 = a[1], x2 = a[2], y2 = a[3];
        s_box[tid]  = make_float4(x1, y1, x2, y2);
        s_area[tid] = (x2 - x1) * (y2 - y1);
        s_lbl[tid]  = a[4];
    }
    __syncthreads();

    float reg_sum = 0.0f, npos = 0.0f, corr = 0.0f;

    if (k < K) {
        const float4 av = *(const float4*)(anc + 4*(size_t)k);
        const float ax1 = av.x, ay1 = av.y, ax2 = av.z, ay2 = av.w;
        const float area_a = (ax2 - ax1) * (ay2 - ay1);

        // argmax of inter/uni via cross-multiplication (division-free)
        float best_in = -1.0f, best_un = 1.0f;
        int   bi = 0;
        #pragma unroll 8
        for (int n = 0; n < NANN; n++) {
            const float4 bb = s_box[n];
            float iw = fmaxf(fminf(ax2, bb.z) - fmaxf(ax1, bb.x), 0.0f);
            float ih = fmaxf(fminf(ay2, bb.w) - fmaxf(ay1, bb.y), 0.0f);
            float inter = iw * ih;
            float uni   = fmaxf(area_a + s_area[n] - inter, 1e-8f);
            if (inter * best_un > best_in * uni) {     // strict > == first-argmax
                best_in = inter; best_un = uni; bi = n;
            }
        }

        const bool pos = (best_in >= 0.5f * best_un);
        const bool neg = (best_in <  0.4f * best_un);
        wbuf[b * MAXK + k] = (pos || neg) ? COEF_NEG : 0.0f;

        if (pos) {
            npos = 1.0f;
            const int state = (int)s_lbl[bi];
            const float4 gb = s_box[bi];
            const float aw  = ax2 - ax1, ah = ay2 - ay1;
            const float acx = ax1 + 0.5f * aw, acy = ay1 + 0.5f * ah;
            const float gw  = fmaxf(gb.z - gb.x, 1.0f);
            const float gh  = fmaxf(gb.w - gb.y, 1.0f);
            const float gcx = gb.x + 0.5f * gw, gcy = gb.y + 0.5f * gh;
            float t0 = (gcx - acx) / aw * 10.0f;
            float t1 = (gcy - acy) / ah * 10.0f;
            float t2 = __logf(gw / aw) * 5.0f;
            float t3 = __logf(gh / ah) * 5.0f;
            const float4 r = *(const float4*)(regs + ((size_t)b * K + k) * 4);
            float d0 = fabsf(t0 - r.x), d1 = fabsf(t1 - r.y);
            float d2 = fabsf(t2 - r.z), d3 = fabsf(t3 - r.w);
            const float th = 1.0f / 9.0f, off = 0.5f / 9.0f;
            reg_sum += (d0 <= th) ? 4.5f * d0 * d0 : d0 - off;
            reg_sum += (d1 <= th) ? 4.5f * d1 * d1 : d1 - off;
            reg_sum += (d2 <= th) ? 4.5f * d2 * d2 : d2 - off;
            reg_sum += (d3 <= th) ? 4.5f * d3 * d3 : d3 - off;

            // swap negative-formula term for positive-formula term (matched class)
            const float p = cls[((size_t)b * K + k) * NC + state];
            corr = COEF_POS * fsqrt_approx(1.0f - p) * flg2_approx(p)
                 - COEF_NEG * fsqrt_approx(p) * flg2_approx(1.0f - p);
        }
    }

    #pragma unroll
    for (int o = 16; o > 0; o >>= 1) {
        corr    += __shfl_down_sync(0xffffffffu, corr, o);
        reg_sum += __shfl_down_sync(0xffffffffu, reg_sum, o);
        npos    += __shfl_down_sync(0xffffffffu, npos, o);
    }
    const int w = tid >> 5, l = tid & 31;
    if (l == 0) { s_red[0][w] = corr; s_red[1][w] = reg_sum; s_red[2][w] = npos; }
    __syncthreads();
    if (tid == 0) {
        float c = 0.0f, r = 0.0f, n = 0.0f;
        #pragma unroll
        for (int i = 0; i < TPB_M / 32; i++) { c += s_red[0][i]; r += s_red[1][i]; n += s_red[2][i]; }
        atomicAdd(&g_acc[b*3+0], c);
        atomicAdd(&g_acc[b*3+1], r);
        atomicAdd(&g_acc[b*3+2], n);
    }
}

// ---------------------------------------------------------------------------
// Kernel 2: pure streaming classification sweep + finalize
// ---------------------------------------------------------------------------
__global__ __launch_bounds__(TPB_S, 3) void sweep_kernel(
    const float* __restrict__ cls,     // [B,K,C]
    float* __restrict__ out,
    int K, int B)
{
    const int b   = blockIdx.y;
    const int s   = blockIdx.x * TPB_S;
    const int tid = threadIdx.x;

    __shared__ float s_w[TPB_S];
    __shared__ float s_red[TPB_S / 32];

    const int k = s + tid;
    s_w[tid] = (k < K) ? wbuf[b * MAXK + k] : 0.0f;
    __syncthreads();

    const float4* p  = (const float4*)cls + (size_t)b * K * C4N + (size_t)s * C4N + tid;
    const int a4 = tid / 20;     // weight row, computed once

    float a0 = 0.0f, a1 = 0.0f, a2 = 0.0f, a3 = 0.0f;
    if (s + TPB_S <= K) {
        // fast path: compile-time immediate offsets, zero index ALU
        #pragma unroll
        for (int it = 0; it < C4N; it++) {
            const float  w = s_w[it * 16 + a4];
            const float4 v = p[it * TPB_S];
            a0 = fmaf(w, fsqrt_approx(v.x) * flg2_approx(1.0f - v.x), a0);
            a1 = fmaf(w, fsqrt_approx(v.y) * flg2_approx(1.0f - v.y), a1);
            a2 = fmaf(w, fsqrt_approx(v.z) * flg2_approx(1.0f - v.z), a2);
            a3 = fmaf(w, fsqrt_approx(v.w) * flg2_approx(1.0f - v.w), a3);
        }
    } else {
        // boundary blocks (8 of 2504): clamp index; OOB anchors have weight 0
        const int gmax = K * C4N - 1 - (s * C4N + tid);
        #pragma unroll
        for (int it = 0; it < C4N; it++) {
            const float  w = s_w[it * 16 + a4];
            const float4 v = p[min(it * TPB_S, gmax)];
            a0 = fmaf(w, fsqrt_approx(v.x) * flg2_approx(1.0f - v.x), a0);
            a1 = fmaf(w, fsqrt_approx(v.y) * flg2_approx(1.0f - v.y), a1);
            a2 = fmaf(w, fsqrt_approx(v.z) * flg2_approx(1.0f - v.z), a2);
            a3 = fmaf(w, fsqrt_approx(v.w) * flg2_approx(1.0f - v.w), a3);
        }
    }
    float cls_sum = (a0 + a1) + (a2 + a3);

    #pragma unroll
    for (int o = 16; o > 0; o >>= 1)
        cls_sum += __shfl_down_sync(0xffffffffu, cls_sum, o);
    const int w = tid >> 5, l = tid & 31;
    if (l == 0) s_red[w] = cls_sum;
    __syncthreads();

    if (tid == 0) {
        float c = 0.0f;
        #pragma unroll
        for (int i = 0; i < TPB_S / 32; i++) c += s_red[i];
        atomicAdd(&g_acc[b*3+0], c);
        __threadfence();

        const unsigned int total = gridDim.x * gridDim.y;
        const unsigned int old = atomicAdd(&g_count, 1u);
        if (old == total - 1u) {
            float cs = 0.0f, rs = 0.0f;
            for (int bb = 0; bb < B; bb++) {
                const float acc_c = atomicAdd(&g_acc[bb*3+0], 0.0f);
                const float acc_r = atomicAdd(&g_acc[bb*3+1], 0.0f);
                const float np    = atomicAdd(&g_acc[bb*3+2], 0.0f);
                cs += acc_c / fmaxf(np, 1.0f);
                rs += (np > 0.0f) ? acc_r / fmaxf(np * 4.0f, 1.0f) : 0.0f;
            }
            out[0] = cs / (float)B;
            out[1] = rs / (float)B;
            for (int i = 0; i < B * 3; i++) g_acc[i] = 0.0f;
            __threadfence();
            g_count = 0u;
            __threadfence();
        }
    }
}

extern "C" void kernel_launch(void* const* d_in, const int* in_sizes, int n_in,
                              void* d_out, int out_size) {
    const float* cls  = (const float*)d_in[0];   // [B,K,C]
    const float* regs = (const float*)d_in[1];   // [B,K,4]
    const float* anc  = (const float*)d_in[2];   // [1,K,4]
    const float* ann  = (const float*)d_in[3];   // [B,NANN,5]

    const int K = in_sizes[2] / 4;
    const int B = in_sizes[3] / (NANN * 5);

    dim3 gm((K + TPB_M - 1) / TPB_M, B);
    match_kernel<<<gm, TPB_M>>>(cls, regs, anc, ann, K);

    dim3 gs((K + TPB_S - 1) / TPB_S, B);
    sweep_kernel<<<gs, TPB_S>>>(cls, (float*)d_out, K, B);
}

// round 6
// speedup vs baseline: 1.2288x; 1.2288x over previous
#include <cuda_runtime.h>

#define TPB 320      // threads per block == anchors per block (16*20)
#define NANN 32
#define NC 80
#define C4N 20       // float4 per anchor
#define MAXB 16

__device__ float g_acc[MAXB * 3];        // per image: cls_sum, reg_sum, num_pos
__device__ unsigned int g_count = 0;     // completed-block counter (self-resetting)

__device__ __forceinline__ float fsqrt_approx(float x) {
    float r; asm("sqrt.approx.f32 %0, %1;" : "=f"(r) : "f"(x)); return r;
}
__device__ __forceinline__ float flg2_approx(float x) {
    float r; asm("lg2.approx.f32 %0, %1;" : "=f"(r) : "f"(x)); return r;
}

#define LN2F 0.6931471805599453f
#define COEF_NEG (-0.75f * LN2F)    // term = COEF * sqrt(p) * lg2(1-p)
#define COEF_POS (-0.25f * LN2F)

__global__ __launch_bounds__(TPB, 3) void focal_fused_kernel(
    const float* __restrict__ cls,     // [B,K,C]
    const float* __restrict__ regs,    // [B,K,4]
    const float* __restrict__ anc,     // [1,K,4]
    const float* __restrict__ ann,     // [B,NANN,5]
    float* __restrict__ out,
    int K, int B)
{
    const int b   = blockIdx.y;
    const int s   = blockIdx.x * TPB;
    const int tid = threadIdx.x;

    __shared__ float4 s_box[NANN];
    __shared__ float  s_area[NANN];
    __shared__ float  s_lbl[NANN];
    __shared__ float  s_w[TPB];
    __shared__ float  s_red[3][TPB / 32];

    // ---- early prefetch: first 4 sweep tiles, issued before any compute ----
    const float4* p = (const float4*)cls + (size_t)b * K * C4N + (size_t)s * C4N + tid;
    const bool interior = (s + TPB <= K);
    const int  gmax = K * C4N - 1 - (s * C4N + tid);   // relative clamp bound
    float4 v0, v1, v2, v3;
    if (interior) {
        v0 = p[0 * TPB]; v1 = p[1 * TPB]; v2 = p[2 * TPB]; v3 = p[3 * TPB];
    } else {
        v0 = p[min(0 * TPB, gmax)]; v1 = p[min(1 * TPB, gmax)];
        v2 = p[min(2 * TPB, gmax)]; v3 = p[min(3 * TPB, gmax)];
    }

    if (tid < NANN) {
        const float* a = ann + (size_t)b * NANN * 5 + tid * 5;
        float x1 = a[0], y1 = a[1], x2 = a[2], y2 = a[3];
        s_box[tid]  = make_float4(x1, y1, x2, y2);
        s_area[tid] = (x2 - x1) * (y2 - y1);
        s_lbl[tid]  = a[4];
    }
    __syncthreads();

    // ---------------- phase 1: IoU match (division-free) + reg loss ----------
    float reg_sum = 0.0f, npos = 0.0f, corr = 0.0f, wgt_me = 0.0f;
    const int k = s + tid;

    if (k < K) {
        const float4 av = *(const float4*)(anc + 4*(size_t)k);
        const float ax1 = av.x, ay1 = av.y, ax2 = av.z, ay2 = av.w;
        const float area_a = (ax2 - ax1) * (ay2 - ay1);

        float best_in = -1.0f, best_un = 1.0f;
        int   bi = 0;
        #pragma unroll 8
        for (int n = 0; n < NANN; n++) {
            const float4 bb = s_box[n];
            float iw = fmaxf(fminf(ax2, bb.z) - fmaxf(ax1, bb.x), 0.0f);
            float ih = fmaxf(fminf(ay2, bb.w) - fmaxf(ay1, bb.y), 0.0f);
            float inter = iw * ih;
            float uni   = fmaxf(area_a + s_area[n] - inter, 1e-8f);
            if (inter * best_un > best_in * uni) {     // strict > == first-argmax
                best_in = inter; best_un = uni; bi = n;
            }
        }

        const bool pos = (best_in >= 0.5f * best_un);
        const bool neg = (best_in <  0.4f * best_un);
        wgt_me = (pos || neg) ? COEF_NEG : 0.0f;

        if (pos) {
            npos = 1.0f;
            const int state = (int)s_lbl[bi];
            const float4 gb = s_box[bi];
            const float aw  = ax2 - ax1, ah = ay2 - ay1;
            const float acx = ax1 + 0.5f * aw, acy = ay1 + 0.5f * ah;
            const float gw  = fmaxf(gb.z - gb.x, 1.0f);
            const float gh  = fmaxf(gb.w - gb.y, 1.0f);
            const float gcx = gb.x + 0.5f * gw, gcy = gb.y + 0.5f * gh;
            float t0 = (gcx - acx) / aw * 10.0f;
            float t1 = (gcy - acy) / ah * 10.0f;
            float t2 = __logf(gw / aw) * 5.0f;
            float t3 = __logf(gh / ah) * 5.0f;
            const float4 r = *(const float4*)(regs + ((size_t)b * K + k) * 4);
            float d0 = fabsf(t0 - r.x), d1 = fabsf(t1 - r.y);
            float d2 = fabsf(t2 - r.z), d3 = fabsf(t3 - r.w);
            const float th = 1.0f / 9.0f, off = 0.5f / 9.0f;
            reg_sum += (d0 <= th) ? 4.5f * d0 * d0 : d0 - off;
            reg_sum += (d1 <= th) ? 4.5f * d1 * d1 : d1 - off;
            reg_sum += (d2 <= th) ? 4.5f * d2 * d2 : d2 - off;
            reg_sum += (d3 <= th) ? 4.5f * d3 * d3 : d3 - off;

            // swap negative-formula term for positive-formula term (matched class)
            const float pc = cls[((size_t)b * K + k) * NC + state];
            corr = COEF_POS * fsqrt_approx(1.0f - pc) * flg2_approx(pc)
                 - COEF_NEG * fsqrt_approx(pc) * flg2_approx(1.0f - pc);
        }
    }
    s_w[tid] = wgt_me;
    __syncthreads();

    // ---------------- phase 2: streaming sweep, 4-deep rolling pipeline ------
    const int a4 = tid / 20;
    float a0 = 0.0f, a1 = 0.0f, a2 = 0.0f, a3 = 0.0f;

    #define PROC(vv, it)                                                      \
        {                                                                     \
            const float w = s_w[(it) * 16 + a4];                              \
            a0 = fmaf(w, fsqrt_approx(vv.x) * flg2_approx(1.0f - vv.x), a0);  \
            a1 = fmaf(w, fsqrt_approx(vv.y) * flg2_approx(1.0f - vv.y), a1);  \
            a2 = fmaf(w, fsqrt_approx(vv.z) * flg2_approx(1.0f - vv.z), a2);  \
            a3 = fmaf(w, fsqrt_approx(vv.w) * flg2_approx(1.0f - vv.w), a3);  \
        }

    if (interior) {
        #pragma unroll
        for (int it = 0; it < C4N; it++) {
            PROC(v0, it);
            v0 = v1; v1 = v2; v2 = v3;
            if (it + 4 < C4N) v3 = p[(it + 4) * TPB];   // compile-time offsets
        }
    } else {
        #pragma unroll
        for (int it = 0; it < C4N; it++) {
            PROC(v0, it);
            v0 = v1; v1 = v2; v2 = v3;
            if (it + 4 < C4N) v3 = p[min((it + 4) * TPB, gmax)];
        }
    }
    #undef PROC
    float cls_sum = ((a0 + a1) + (a2 + a3)) + corr;

    // ---------------- block reduction + finalize -------------------------------
    #pragma unroll
    for (int o = 16; o > 0; o >>= 1) {
        cls_sum += __shfl_down_sync(0xffffffffu, cls_sum, o);
        reg_sum += __shfl_down_sync(0xffffffffu, reg_sum, o);
        npos    += __shfl_down_sync(0xffffffffu, npos, o);
    }
    const int w = tid >> 5, l = tid & 31;
    if (l == 0) { s_red[0][w] = cls_sum; s_red[1][w] = reg_sum; s_red[2][w] = npos; }
    __syncthreads();

    if (tid == 0) {
        float c = 0.0f, r = 0.0f, n = 0.0f;
        #pragma unroll
        for (int i = 0; i < TPB / 32; i++) { c += s_red[0][i]; r += s_red[1][i]; n += s_red[2][i]; }
        atomicAdd(&g_acc[b*3+0], c);
        atomicAdd(&g_acc[b*3+1], r);
        atomicAdd(&g_acc[b*3+2], n);
        __threadfence();

        const unsigned int total = gridDim.x * gridDim.y;
        const unsigned int old = atomicAdd(&g_count, 1u);
        if (old == total - 1u) {
            float cs = 0.0f, rs = 0.0f;
            for (int bb = 0; bb < B; bb++) {
                const float acc_c = atomicAdd(&g_acc[bb*3+0], 0.0f);
                const float acc_r = atomicAdd(&g_acc[bb*3+1], 0.0f);
                const float np    = atomicAdd(&g_acc[bb*3+2], 0.0f);
                cs += acc_c / fmaxf(np, 1.0f);
                rs += (np > 0.0f) ? acc_r / fmaxf(np * 4.0f, 1.0f) : 0.0f;
            }
            out[0] = cs / (float)B;
            out[1] = rs / (float)B;
            for (int i = 0; i < B * 3; i++) g_acc[i] = 0.0f;
            __threadfence();
            g_count = 0u;
            __threadfence();
        }
    }
}

extern "C" void kernel_launch(void* const* d_in, const int* in_sizes, int n_in,
                              void* d_out, int out_size) {
    const float* cls  = (const float*)d_in[0];   // [B,K,C]
    const float* regs = (const float*)d_in[1];   // [B,K,4]
    const float* anc  = (const float*)d_in[2];   // [1,K,4]
    const float* ann  = (const float*)d_in[3];   // [B,NANN,5]

    const int K = in_sizes[2] / 4;
    const int B = in_sizes[3] / (NANN * 5);

    dim3 grid((K + TPB - 1) / TPB, B);
    focal_fused_kernel<<<grid, TPB>>>(cls, regs, anc, ann, (float*)d_out, K, B);
}

// round 7
// speedup vs baseline: 1.2726x; 1.0356x over previous
#include <cuda_runtime.h>

#define TPB 320      // threads per block == anchors per block (16*20)
#define NANN 32
#define NC 80
#define C4N 20       // float4 per anchor
#define MAXB 16

__device__ float g_acc[MAXB * 3];        // per image: cls_sum, reg_sum, num_pos
__device__ unsigned int g_count = 0;     // completed-block counter (self-resetting)

typedef unsigned long long u64;

__device__ __forceinline__ float fsqrt_approx(float x) {
    float r; asm("sqrt.approx.f32 %0, %1;" : "=f"(r) : "f"(x)); return r;
}
__device__ __forceinline__ float flg2_approx(float x) {
    float r; asm("lg2.approx.f32 %0, %1;" : "=f"(r) : "f"(x)); return r;
}
__device__ __forceinline__ u64 pack2(float lo, float hi) {
    u64 r; asm("mov.b64 %0, {%1, %2};" : "=l"(r) : "f"(lo), "f"(hi)); return r;
}
__device__ __forceinline__ void unpack2(u64 v, float& lo, float& hi) {
    asm("mov.b64 {%0, %1}, %2;" : "=f"(lo), "=f"(hi) : "l"(v));
}
__device__ __forceinline__ u64 fma2(u64 a, u64 b, u64 c) {
    u64 d; asm("fma.rn.f32x2 %0, %1, %2, %3;" : "=l"(d) : "l"(a), "l"(b), "l"(c)); return d;
}
__device__ __forceinline__ u64 mul2(u64 a, u64 b) {
    u64 d; asm("mul.rn.f32x2 %0, %1, %2;" : "=l"(d) : "l"(a), "l"(b)); return d;
}

#define LN2F 0.6931471805599453f
#define COEF_NEG (-0.75f * LN2F)    // term = COEF * sqrt(p) * lg2(1-p)
#define COEF_POS (-0.25f * LN2F)

__global__ __launch_bounds__(TPB, 3) void focal_fused_kernel(
    const float* __restrict__ cls,     // [B,K,C]
    const float* __restrict__ regs,    // [B,K,4]
    const float* __restrict__ anc,     // [1,K,4]
    const float* __restrict__ ann,     // [B,NANN,5]
    float* __restrict__ out,
    int K, int B)
{
    const int b   = blockIdx.y;
    const int s   = blockIdx.x * TPB;
    const int tid = threadIdx.x;

    __shared__ float4 s_box[NANN];
    __shared__ float  s_area[NANN];
    __shared__ float  s_lbl[NANN];
    __shared__ float  s_w[TPB];
    __shared__ float  s_red[3][TPB / 32];

    // ---- early prefetch: first 4 sweep tiles, single-use (no shift MOVs) ----
    const ulonglong2* p = (const ulonglong2*)cls + (size_t)b * K * C4N
                        + (size_t)s * C4N + tid;
    const bool interior = (s + TPB <= K);
    const int  gmax = K * C4N - 1 - (s * C4N + tid);   // relative clamp bound
    ulonglong2 pf0, pf1, pf2, pf3;
    if (interior) {
        pf0 = p[0 * TPB]; pf1 = p[1 * TPB]; pf2 = p[2 * TPB]; pf3 = p[3 * TPB];
    } else {
        pf0 = p[min(0 * TPB, gmax)]; pf1 = p[min(1 * TPB, gmax)];
        pf2 = p[min(2 * TPB, gmax)]; pf3 = p[min(3 * TPB, gmax)];
    }

    if (tid < NANN) {
        const float* a = ann + (size_t)b * NANN * 5 + tid * 5;
        float x1 = a[0], y1 = a[1], x2 = a[2], y2 = a[3];
        s_box[tid]  = make_float4(x1, y1, x2, y2);
        s_area[tid] = (x2 - x1) * (y2 - y1);
        s_lbl[tid]  = a[4];
    }
    __syncthreads();

    // ---------------- phase 1: IoU match (division-free) + reg loss ----------
    float reg_sum = 0.0f, npos = 0.0f, corr = 0.0f, wgt_me = 0.0f;
    const int k = s + tid;

    if (k < K) {
        const float4 av = *(const float4*)(anc + 4*(size_t)k);
        const float ax1 = av.x, ay1 = av.y, ax2 = av.z, ay2 = av.w;
        const float area_a = (ax2 - ax1) * (ay2 - ay1);

        float best_in = -1.0f, best_un = 1.0f;
        int   bi = 0;
        #pragma unroll 8
        for (int n = 0; n < NANN; n++) {
            const float4 bb = s_box[n];
            float iw = fmaxf(fminf(ax2, bb.z) - fmaxf(ax1, bb.x), 0.0f);
            float ih = fmaxf(fminf(ay2, bb.w) - fmaxf(ay1, bb.y), 0.0f);
            float inter = iw * ih;
            float uni   = fmaxf(area_a + s_area[n] - inter, 1e-8f);
            if (inter * best_un > best_in * uni) {     // strict > == first-argmax
                best_in = inter; best_un = uni; bi = n;
            }
        }

        const bool pos = (best_in >= 0.5f * best_un);
        const bool neg = (best_in <  0.4f * best_un);
        wgt_me = (pos || neg) ? COEF_NEG : 0.0f;

        if (pos) {
            npos = 1.0f;
            const int state = (int)s_lbl[bi];
            const float4 gb = s_box[bi];
            const float aw  = ax2 - ax1, ah = ay2 - ay1;
            const float acx = ax1 + 0.5f * aw, acy = ay1 + 0.5f * ah;
            const float gw  = fmaxf(gb.z - gb.x, 1.0f);
            const float gh  = fmaxf(gb.w - gb.y, 1.0f);
            const float gcx = gb.x + 0.5f * gw, gcy = gb.y + 0.5f * gh;
            float t0 = (gcx - acx) / aw * 10.0f;
            float t1 = (gcy - acy) / ah * 10.0f;
            float t2 = __logf(gw / aw) * 5.0f;
            float t3 = __logf(gh / ah) * 5.0f;
            const float4 r = *(const float4*)(regs + ((size_t)b * K + k) * 4);
            float d0 = fabsf(t0 - r.x), d1 = fabsf(t1 - r.y);
            float d2 = fabsf(t2 - r.z), d3 = fabsf(t3 - r.w);
            const float th = 1.0f / 9.0f, off = 0.5f / 9.0f;
            reg_sum += (d0 <= th) ? 4.5f * d0 * d0 : d0 - off;
            reg_sum += (d1 <= th) ? 4.5f * d1 * d1 : d1 - off;
            reg_sum += (d2 <= th) ? 4.5f * d2 * d2 : d2 - off;
            reg_sum += (d3 <= th) ? 4.5f * d3 * d3 : d3 - off;

            // swap negative-formula term for positive-formula term (matched class)
            const float pc = cls[((size_t)b * K + k) * NC + state];
            corr = COEF_POS * fsqrt_approx(1.0f - pc) * flg2_approx(pc)
                 - COEF_NEG * fsqrt_approx(pc) * flg2_approx(1.0f - pc);
        }
    }
    s_w[tid] = wgt_me;
    __syncthreads();

    // ---------------- phase 2: streaming sweep, packed f32x2 math ------------
    const int a4 = tid / 20;
    const u64 ONE2 = pack2(1.0f, 1.0f);
    const u64 NEG2 = pack2(-1.0f, -1.0f);
    u64 acc0 = 0ull, acc1 = 0ull;   // f32x2 accumulators (0,0)

    #define PROC(vv, it)                                                     \
        {                                                                    \
            const float w = s_w[(it) * 16 + a4];                             \
            const u64 w2 = pack2(w, w);                                      \
            u64 qa = fma2(vv.x, NEG2, ONE2);   /* (1-p0, 1-p1) */            \
            u64 qb = fma2(vv.y, NEG2, ONE2);                                 \
            float p0, p1, p2, p3, q0, q1, q2, q3;                            \
            unpack2(vv.x, p0, p1); unpack2(vv.y, p2, p3);                    \
            unpack2(qa, q0, q1);   unpack2(qb, q2, q3);                      \
            u64 sa = pack2(fsqrt_approx(p0), fsqrt_approx(p1));              \
            u64 sb = pack2(fsqrt_approx(p2), fsqrt_approx(p3));              \
            u64 la = pack2(flg2_approx(q0), flg2_approx(q1));                \
            u64 lb = pack2(flg2_approx(q2), flg2_approx(q3));                \
            acc0 = fma2(w2, mul2(sa, la), acc0);                             \
            acc1 = fma2(w2, mul2(sb, lb), acc1);                             \
        }

    if (interior) {
        PROC(pf0, 0); PROC(pf1, 1); PROC(pf2, 2); PROC(pf3, 3);
        #pragma unroll
        for (int it = 4; it < C4N; it++) {
            const ulonglong2 vv = p[it * TPB];       // compile-time offsets
            PROC(vv, it);
        }
    } else {
        PROC(pf0, 0); PROC(pf1, 1); PROC(pf2, 2); PROC(pf3, 3);
        #pragma unroll
        for (int it = 4; it < C4N; it++) {
            const ulonglong2 vv = p[min(it * TPB, gmax)];
            PROC(vv, it);
        }
    }
    #undef PROC

    float c0, c1, c2, c3;
    unpack2(acc0, c0, c1);
    unpack2(acc1, c2, c3);
    float cls_sum = ((c0 + c1) + (c2 + c3)) + corr;

    // ---------------- block reduction + finalize ------------------------------
    #pragma unroll
    for (int o = 16; o > 0; o >>= 1) {
        cls_sum += __shfl_down_sync(0xffffffffu, cls_sum, o);
        reg_sum += __shfl_down_sync(0xffffffffu, reg_sum, o);
        npos    += __shfl_down_sync(0xffffffffu, npos, o);
    }
    const int w = tid >> 5, l = tid & 31;
    if (l == 0) { s_red[0][w] = cls_sum; s_red[1][w] = reg_sum; s_red[2][w] = npos; }
    __syncthreads();

    if (tid == 0) {
        float c = 0.0f, r = 0.0f, n = 0.0f;
        #pragma unroll
        for (int i = 0; i < TPB / 32; i++) { c += s_red[0][i]; r += s_red[1][i]; n += s_red[2][i]; }
        atomicAdd(&g_acc[b*3+0], c);
        atomicAdd(&g_acc[b*3+1], r);
        atomicAdd(&g_acc[b*3+2], n);
        __threadfence();

        const unsigned int total = gridDim.x * gridDim.y;
        const unsigned int old = atomicAdd(&g_count, 1u);
        if (old == total - 1u) {
            float cs = 0.0f, rs = 0.0f;
            for (int bb = 0; bb < B; bb++) {
                const float acc_c = atomicAdd(&g_acc[bb*3+0], 0.0f);
                const float acc_r = atomicAdd(&g_acc[bb*3+1], 0.0f);
                const float np    = atomicAdd(&g_acc[bb*3+2], 0.0f);
                cs += acc_c / fmaxf(np, 1.0f);
                rs += (np > 0.0f) ? acc_r / fmaxf(np * 4.0f, 1.0f) : 0.0f;
            }
            out[0] = cs / (float)B;
            out[1] = rs / (float)B;
            for (int i = 0; i < B * 3; i++) g_acc[i] = 0.0f;
            __threadfence();
            g_count = 0u;
            __threadfence();
        }
    }
}

extern "C" void kernel_launch(void* const* d_in, const int* in_sizes, int n_in,
                              void* d_out, int out_size) {
    const float* cls  = (const float*)d_in[0];   // [B,K,C]
    const float* regs = (const float*)d_in[1];   // [B,K,4]
    const float* anc  = (const float*)d_in[2];   // [1,K,4]
    const float* ann  = (const float*)d_in[3];   // [B,NANN,5]

    const int K = in_sizes[2] / 4;
    const int B = in_sizes[3] / (NANN * 5);

    dim3 grid((K + TPB - 1) / TPB, B);
    focal_fused_kernel<<<grid, TPB>>>(cls, regs, anc, ann, (float*)d_out, K, B);
}

// round 8
// speedup vs baseline: 1.3175x; 1.0353x over previous
#include <cuda_runtime.h>

#define TPB 256      // 8 warps; each warp owns 32 anchors
#define NANN 32
#define NC 80
#define C4N 20       // float4 per anchor
#define MAXB 16

__device__ float g_acc[MAXB * 3];        // per image: cls_sum, reg_sum, num_pos
__device__ unsigned int g_count = 0;     // completed-block counter (self-resetting)

__device__ __forceinline__ float fsqrt_approx(float x) {
    float r; asm("sqrt.approx.f32 %0, %1;" : "=f"(r) : "f"(x)); return r;
}
__device__ __forceinline__ float flg2_approx(float x) {
    float r; asm("lg2.approx.f32 %0, %1;" : "=f"(r) : "f"(x)); return r;
}

#define LN2F 0.6931471805599453f
#define COEF_NEG (-0.75f * LN2F)    // term = COEF * sqrt(p) * lg2(1-p)
#define COEF_POS (-0.25f * LN2F)

__global__ __launch_bounds__(TPB, 5) void focal_fused_kernel(
    const float* __restrict__ cls,     // [B,K,C]
    const float* __restrict__ regs,    // [B,K,4]
    const float* __restrict__ anc,     // [1,K,4]
    const float* __restrict__ ann,     // [B,NANN,5]
    float* __restrict__ out,
    int K, int B)
{
    const int b    = blockIdx.y;
    const int s    = blockIdx.x * TPB;
    const int tid  = threadIdx.x;
    const int wid  = tid >> 5;
    const int lane = tid & 31;

    __shared__ float4 s_box[NANN];
    __shared__ float  s_area[NANN];
    __shared__ float  s_lbl[NANN];
    __shared__ float  s_red[3][TPB / 32];

    if (tid < NANN) {
        const float* a = ann + (size_t)b * NANN * 5 + tid * 5;
        float x1 = a[0], y1 = a[1], x2 = a[2], y2 = a[3];
        s_box[tid]  = make_float4(x1, y1, x2, y2);
        s_area[tid] = (x2 - x1) * (y2 - y1);
        s_lbl[tid]  = a[4];
    }
    __syncthreads();   // the ONLY barrier before heavy work

    const int base = s + (wid << 5);     // this warp's first anchor
    const int k    = base + lane;

    // ---------------- phase 1: IoU match (division-free) + reg loss ----------
    // No block barrier follows: ptxas may hoist the sweep's LDGs under this.
    float reg_sum = 0.0f, npos = 0.0f, corr = 0.0f, wgt = 0.0f;

    if (k < K) {
        const float4 av = *(const float4*)(anc + 4*(size_t)k);
        const float ax1 = av.x, ay1 = av.y, ax2 = av.z, ay2 = av.w;
        const float area_a = (ax2 - ax1) * (ay2 - ay1);

        float best_in = -1.0f, best_un = 1.0f;
        int   bi = 0;
        #pragma unroll 8
        for (int n = 0; n < NANN; n++) {
            const float4 bb = s_box[n];
            float iw = fmaxf(fminf(ax2, bb.z) - fmaxf(ax1, bb.x), 0.0f);
            float ih = fmaxf(fminf(ay2, bb.w) - fmaxf(ay1, bb.y), 0.0f);
            float inter = iw * ih;
            float uni   = fmaxf(area_a + s_area[n] - inter, 1e-8f);
            if (inter * best_un > best_in * uni) {     // strict > == first-argmax
                best_in = inter; best_un = uni; bi = n;
            }
        }

        const bool pos = (best_in >= 0.5f * best_un);
        const bool neg = (best_in <  0.4f * best_un);
        wgt = (pos || neg) ? COEF_NEG : 0.0f;

        if (pos) {
            npos = 1.0f;
            const int state = (int)s_lbl[bi];
            const float4 gb = s_box[bi];
            const float aw  = ax2 - ax1, ah = ay2 - ay1;
            const float acx = ax1 + 0.5f * aw, acy = ay1 + 0.5f * ah;
            const float gw  = fmaxf(gb.z - gb.x, 1.0f);
            const float gh  = fmaxf(gb.w - gb.y, 1.0f);
            const float gcx = gb.x + 0.5f * gw, gcy = gb.y + 0.5f * gh;
            float t0 = (gcx - acx) / aw * 10.0f;
            float t1 = (gcy - acy) / ah * 10.0f;
            float t2 = __logf(gw / aw) * 5.0f;
            float t3 = __logf(gh / ah) * 5.0f;
            const float4 r = *(const float4*)(regs + ((size_t)b * K + k) * 4);
            float d0 = fabsf(t0 - r.x), d1 = fabsf(t1 - r.y);
            float d2 = fabsf(t2 - r.z), d3 = fabsf(t3 - r.w);
            const float th = 1.0f / 9.0f, off = 0.5f / 9.0f;
            reg_sum += (d0 <= th) ? 4.5f * d0 * d0 : d0 - off;
            reg_sum += (d1 <= th) ? 4.5f * d1 * d1 : d1 - off;
            reg_sum += (d2 <= th) ? 4.5f * d2 * d2 : d2 - off;
            reg_sum += (d3 <= th) ? 4.5f * d3 * d3 : d3 - off;

            // swap negative-formula term for positive-formula term (matched class)
            const float pc = cls[((size_t)b * K + k) * NC + state];
            corr = COEF_POS * fsqrt_approx(1.0f - pc) * flg2_approx(pc)
                 - COEF_NEG * fsqrt_approx(pc) * flg2_approx(1.0f - pc);
        }
    }

    // ---------------- phase 2: warp-local sweep (weights via shuffle) --------
    // warp covers float4 range [base*20, base*20+640): iter it reads
    // idx = it*32 + lane (coalesced); anchor of element = (it*32+lane)/20.
    float a0 = 0.0f, a1 = 0.0f, a2 = 0.0f, a3 = 0.0f;

    #define PROC(vv, wv)                                                      \
        {                                                                     \
            a0 = fmaf(wv, fsqrt_approx(vv.x) * flg2_approx(1.0f - vv.x), a0); \
            a1 = fmaf(wv, fsqrt_approx(vv.y) * flg2_approx(1.0f - vv.y), a1); \
            a2 = fmaf(wv, fsqrt_approx(vv.z) * flg2_approx(1.0f - vv.z), a2); \
            a3 = fmaf(wv, fsqrt_approx(vv.w) * flg2_approx(1.0f - vv.w), a3); \
        }

    if (base + 32 <= K) {
        // full warp: no bounds checks at all, compile-time immediate offsets
        const float4* p = (const float4*)cls + (size_t)b * K * C4N
                        + (size_t)base * C4N + lane;
        #pragma unroll
        for (int it = 0; it < C4N; it++) {
            const int   a_loc = (it * 32 + lane) / 20;      // 0..31
            const float w     = __shfl_sync(0xffffffffu, wgt, a_loc);
            const float4 v    = p[it * 32];
            PROC(v, w);
        }
    } else if (base < K) {
        // partial warp (only if K%32 != 0): clamp loads; OOB lanes have wgt=0
        const float4* p = (const float4*)cls + (size_t)b * K * C4N
                        + (size_t)base * C4N + lane;
        const int rmax = (K - base) * C4N - 1 - lane;
        #pragma unroll
        for (int it = 0; it < C4N; it++) {
            const int   a_loc = (it * 32 + lane) / 20;
            const float w     = __shfl_sync(0xffffffffu, wgt, a_loc);
            const float4 v    = p[max(min(it * 32, rmax), 0)];
            PROC(v, w);
        }
    }
    #undef PROC
    float cls_sum = ((a0 + a1) + (a2 + a3)) + corr;

    // ---------------- block reduction + finalize ------------------------------
    #pragma unroll
    for (int o = 16; o > 0; o >>= 1) {
        cls_sum += __shfl_down_sync(0xffffffffu, cls_sum, o);
        reg_sum += __shfl_down_sync(0xffffffffu, reg_sum, o);
        npos    += __shfl_down_sync(0xffffffffu, npos, o);
    }
    if (lane == 0) { s_red[0][wid] = cls_sum; s_red[1][wid] = reg_sum; s_red[2][wid] = npos; }
    __syncthreads();

    if (tid == 0) {
        float c = 0.0f, r = 0.0f, n = 0.0f;
        #pragma unroll
        for (int i = 0; i < TPB / 32; i++) { c += s_red[0][i]; r += s_red[1][i]; n += s_red[2][i]; }
        atomicAdd(&g_acc[b*3+0], c);
        atomicAdd(&g_acc[b*3+1], r);
        atomicAdd(&g_acc[b*3+2], n);
        __threadfence();

        const unsigned int total = gridDim.x * gridDim.y;
        const unsigned int old = atomicAdd(&g_count, 1u);
        if (old == total - 1u) {
            float cs = 0.0f, rs = 0.0f;
            for (int bb = 0; bb < B; bb++) {
                const float acc_c = atomicAdd(&g_acc[bb*3+0], 0.0f);
                const float acc_r = atomicAdd(&g_acc[bb*3+1], 0.0f);
                const float np    = atomicAdd(&g_acc[bb*3+2], 0.0f);
                cs += acc_c / fmaxf(np, 1.0f);
                rs += (np > 0.0f) ? acc_r / fmaxf(np * 4.0f, 1.0f) : 0.0f;
            }
            out[0] = cs / (float)B;
            out[1] = rs / (float)B;
            for (int i = 0; i < B * 3; i++) g_acc[i] = 0.0f;
            __threadfence();
            g_count = 0u;
            __threadfence();
        }
    }
}

extern "C" void kernel_launch(void* const* d_in, const int* in_sizes, int n_in,
                              void* d_out, int out_size) {
    const float* cls  = (const float*)d_in[0];   // [B,K,C]
    const float* regs = (const float*)d_in[1];   // [B,K,4]
    const float* anc  = (const float*)d_in[2];   // [1,K,4]
    const float* ann  = (const float*)d_in[3];   // [B,NANN,5]

    const int K = in_sizes[2] / 4;
    const int B = in_sizes[3] / (NANN * 5);

    dim3 grid((K + TPB - 1) / TPB, B);
    focal_fused_kernel<<<grid, TPB>>>(cls, regs, anc, ann, (float*)d_out, K, B);
}

// round 9
// speedup vs baseline: 1.3748x; 1.0435x over previous
#include <cuda_runtime.h>

#define TPB 256      // 8 warps; each warp owns 32 anchors
#define NANN 32
#define NC 80
#define C4N 20       // float4 per anchor
#define MAXB 16

__device__ float g_acc[MAXB * 3];        // per image: cls_sum, reg_sum, num_pos
__device__ unsigned int g_count = 0;     // completed-block counter (self-resetting)

__device__ __forceinline__ float fsqrt_approx(float x) {
    float r; asm("sqrt.approx.f32 %0, %1;" : "=f"(r) : "f"(x)); return r;
}
__device__ __forceinline__ float flg2_approx(float x) {
    float r; asm("lg2.approx.f32 %0, %1;" : "=f"(r) : "f"(x)); return r;
}

#define LN2F 0.6931471805599453f
#define COEF_NEG (-0.75f * LN2F)    // term = COEF * sqrt(p) * lg2(1-p)
#define COEF_POS (-0.25f * LN2F)

__global__ __launch_bounds__(TPB, 6) void focal_fused_kernel(
    const float* __restrict__ cls,     // [B,K,C]
    const float* __restrict__ regs,    // [B,K,4]
    const float* __restrict__ anc,     // [1,K,4]
    const float* __restrict__ ann,     // [B,NANN,5]
    float* __restrict__ out,
    int K, int B)
{
    const int b    = blockIdx.y;
    const int s    = blockIdx.x * TPB;
    const int tid  = threadIdx.x;
    const int wid  = tid >> 5;
    const int lane = tid & 31;

    __shared__ float4 s_box[NANN];
    __shared__ float  s_area[NANN];
    __shared__ float  s_lbl[NANN];
    __shared__ float  s_red[3][TPB / 32];

    if (tid < NANN) {
        const float* a = ann + (size_t)b * NANN * 5 + tid * 5;
        float x1 = a[0], y1 = a[1], x2 = a[2], y2 = a[3];
        s_box[tid]  = make_float4(x1, y1, x2, y2);
        s_area[tid] = (x2 - x1) * (y2 - y1);
        s_lbl[tid]  = a[4];
    }
    __syncthreads();   // the ONLY block barrier before heavy work

    const int base = s + (wid << 5);     // this warp's first anchor
    const int k    = base + lane;

    // ---------------- phase 1: IoU match (division-free) + reg loss ----------
    float reg_sum = 0.0f, npos = 0.0f, corr = 0.0f, wgt = 0.0f;

    if (k < K) {
        const float4 av = *(const float4*)(anc + 4*(size_t)k);
        const float ax1 = av.x, ay1 = av.y, ax2 = av.z, ay2 = av.w;
        const float area_a = (ax2 - ax1) * (ay2 - ay1);

        float best_in = -1.0f, best_un = 1.0f;
        int   bi = 0;
        #pragma unroll 8
        for (int n = 0; n < NANN; n++) {
            const float4 bb = s_box[n];
            float iw = fmaxf(fminf(ax2, bb.z) - fmaxf(ax1, bb.x), 0.0f);
            float ih = fmaxf(fminf(ay2, bb.w) - fmaxf(ay1, bb.y), 0.0f);
            float inter = iw * ih;
            float uni   = area_a + s_area[n] - inter;   // always >= 256 here
            if (inter * best_un > best_in * uni) {      // strict > == first-argmax
                best_in = inter; best_un = uni; bi = n;
            }
        }

        const bool pos = (best_in >= 0.5f * best_un);
        const bool neg = (best_in <  0.4f * best_un);
        wgt = (pos || neg) ? COEF_NEG : 0.0f;

        if (pos) {
            npos = 1.0f;
            const int state = (int)s_lbl[bi];
            const float4 gb = s_box[bi];
            const float aw  = ax2 - ax1, ah = ay2 - ay1;
            const float acx = ax1 + 0.5f * aw, acy = ay1 + 0.5f * ah;
            const float gw  = fmaxf(gb.z - gb.x, 1.0f);
            const float gh  = fmaxf(gb.w - gb.y, 1.0f);
            const float gcx = gb.x + 0.5f * gw, gcy = gb.y + 0.5f * gh;
            float t0 = (gcx - acx) / aw * 10.0f;
            float t1 = (gcy - acy) / ah * 10.0f;
            float t2 = __logf(gw / aw) * 5.0f;
            float t3 = __logf(gh / ah) * 5.0f;
            const float4 r = *(const float4*)(regs + ((size_t)b * K + k) * 4);
            float d0 = fabsf(t0 - r.x), d1 = fabsf(t1 - r.y);
            float d2 = fabsf(t2 - r.z), d3 = fabsf(t3 - r.w);
            const float th = 1.0f / 9.0f, off = 0.5f / 9.0f;
            reg_sum += (d0 <= th) ? 4.5f * d0 * d0 : d0 - off;
            reg_sum += (d1 <= th) ? 4.5f * d1 * d1 : d1 - off;
            reg_sum += (d2 <= th) ? 4.5f * d2 * d2 : d2 - off;
            reg_sum += (d3 <= th) ? 4.5f * d3 * d3 : d3 - off;

            // swap negative-formula term for positive-formula term (matched class)
            const float pc = cls[((size_t)b * K + k) * NC + state];
            corr = COEF_POS * fsqrt_approx(1.0f - pc) * flg2_approx(pc)
                 - COEF_NEG * fsqrt_approx(pc) * flg2_approx(1.0f - pc);
        }
    }

    // ---------------- phase 2: anchor-aligned sweep ---------------------------
    // 4 lanes per anchor. outer o = 0..3 covers anchors [o*8, o*8+8) of this warp,
    // 5 load-iters each. Weight: ONE shuffle per outer, ONE FFMA per anchor-partial.
    float cls_sum = corr;
    const int quad = lane >> 2;      // 0..7  : anchor within group
    const int qlan = lane & 3;       // 0..3  : f4 slot within anchor

    if (base + 32 <= K) {
        const float4* p = (const float4*)cls + (size_t)b * K * C4N
                        + (size_t)(base + quad) * C4N + qlan;
        #pragma unroll
        for (int o = 0; o < 4; o++) {
            const float w = __shfl_sync(0xffffffffu, wgt, o * 8 + quad);
            float b0 = 0.0f, b1 = 0.0f, b2 = 0.0f, b3 = 0.0f;
            #pragma unroll
            for (int it = 0; it < 5; it++) {
                const float4 v = p[o * 160 + it * 4];   // immediate offsets
                b0 += fsqrt_approx(v.x) * flg2_approx(1.0f - v.x);
                b1 += fsqrt_approx(v.y) * flg2_approx(1.0f - v.y);
                b2 += fsqrt_approx(v.z) * flg2_approx(1.0f - v.z);
                b3 += fsqrt_approx(v.w) * flg2_approx(1.0f - v.w);
            }
            cls_sum = fmaf(w, (b0 + b1) + (b2 + b3), cls_sum);
        }
    } else if (base < K) {
        // partial warp (K % 32 != 0 only): masked per-element fallback
        const float4* p = (const float4*)cls + (size_t)b * K * C4N
                        + (size_t)base * C4N + lane;
        const int rmax = (K - base) * C4N - 1 - lane;
        for (int it = 0; it < C4N; it++) {
            const int   a_loc = (it * 32 + lane) / 20;
            const float w     = __shfl_sync(0xffffffffu, wgt, a_loc);
            const float4 v    = p[max(min(it * 32, rmax), 0)];
            cls_sum = fmaf(w, fsqrt_approx(v.x) * flg2_approx(1.0f - v.x), cls_sum);
            cls_sum = fmaf(w, fsqrt_approx(v.y) * flg2_approx(1.0f - v.y), cls_sum);
            cls_sum = fmaf(w, fsqrt_approx(v.z) * flg2_approx(1.0f - v.z), cls_sum);
            cls_sum = fmaf(w, fsqrt_approx(v.w) * flg2_approx(1.0f - v.w), cls_sum);
        }
    }

    // ---------------- block reduction + finalize ------------------------------
    #pragma unroll
    for (int o = 16; o > 0; o >>= 1) {
        cls_sum += __shfl_down_sync(0xffffffffu, cls_sum, o);
        reg_sum += __shfl_down_sync(0xffffffffu, reg_sum, o);
        npos    += __shfl_down_sync(0xffffffffu, npos, o);
    }
    if (lane == 0) { s_red[0][wid] = cls_sum; s_red[1][wid] = reg_sum; s_red[2][wid] = npos; }
    __syncthreads();

    if (tid == 0) {
        float c = 0.0f, r = 0.0f, n = 0.0f;
        #pragma unroll
        for (int i = 0; i < TPB / 32; i++) { c += s_red[0][i]; r += s_red[1][i]; n += s_red[2][i]; }
        atomicAdd(&g_acc[b*3+0], c);
        atomicAdd(&g_acc[b*3+1], r);
        atomicAdd(&g_acc[b*3+2], n);
        __threadfence();

        const unsigned int total = gridDim.x * gridDim.y;
        const unsigned int old = atomicAdd(&g_count, 1u);
        if (old == total - 1u) {
            float cs = 0.0f, rs = 0.0f;
            for (int bb = 0; bb < B; bb++) {
                const float acc_c = atomicAdd(&g_acc[bb*3+0], 0.0f);
                const float acc_r = atomicAdd(&g_acc[bb*3+1], 0.0f);
                const float np    = atomicAdd(&g_acc[bb*3+2], 0.0f);
                cs += acc_c / fmaxf(np, 1.0f);
                rs += (np > 0.0f) ? acc_r / fmaxf(np * 4.0f, 1.0f) : 0.0f;
            }
            out[0] = cs / (float)B;
            out[1] = rs / (float)B;
            for (int i = 0; i < B * 3; i++) g_acc[i] = 0.0f;
            __threadfence();
            g_count = 0u;
            __threadfence();
        }
    }
}

extern "C" void kernel_launch(void* const* d_in, const int* in_sizes, int n_in,
                              void* d_out, int out_size) {
    const float* cls  = (const float*)d_in[0];   // [B,K,C]
    const float* regs = (const float*)d_in[1];   // [B,K,4]
    const float* anc  = (const float*)d_in[2];   // [1,K,4]
    const float* ann  = (const float*)d_in[3];   // [B,NANN,5]

    const int K = in_sizes[2] / 4;
    const int B = in_sizes[3] / (NANN * 5);

    dim3 grid((K + TPB - 1) / TPB, B);
    focal_fused_kernel<<<grid, TPB>>>(cls, regs, anc, ann, (float*)d_out, K, B);
}